// round 11
// baseline (speedup 1.0000x reference)
#include <cuda_runtime.h>
#include <cuda_fp16.h>
#include <cuda_bf16.h>
#include <math.h>

#define NTOK 1280
#define DMOD 512
#define NH   16
#define DH   32
#define DFF  2048
#define NITER 20
#define NSTRIPE 80           // sinkhorn stripes (16 rows each)
#define WCOLS 40             // W: 32 V + 3 x + 1 ones + 4 pad
#define TW 1288              // smem tile row stride in halves (1280 + 8 pad)

// ---------------- scratch ----------------
__device__ __nv_bfloat16 g_EK[NH*NTOK*NTOK];  // exp(logK), bf16
__device__ __nv_bfloat16 g_Wt[NH*WCOLS*NTOK]; // W^T per head: [d][m]
__device__ float g_cpart[NH*NSTRIPE*NTOK];    // sinkhorn col partials (26.2 MB)
__device__ float g_hn  [NTOK*DMOD];
__device__ float g_qkvg[NTOK*4*DMOD];         // [q | k | v | gate]
__device__ float g_lu [NH*NTOK];
__device__ float g_lv [NH*NTOK];
__device__ float g_eu [NH*NTOK];
__device__ float g_ev [NH*NTOK];
__device__ float g_xc [NH*NTOK*3];
__device__ float g_rows[NH*NTOK];
__device__ float g_o  [NTOK*DMOD];
__device__ float g_h2 [NTOK*DMOD];
__device__ float g_hf [NTOK*DMOD];
__device__ float g_t12[NTOK*2*DFF];
__device__ float g_t1 [NTOK*DFF];
__device__ float g_part[4*NTOK*DMOD];         // split-K GEMM partials

__constant__ float c_eps[NH] = {0.5f,0.5f,0.5f,0.5f, 1.f,1.f,1.f,1.f,
                                2.f,2.f,2.f,2.f, 4.f,4.f,4.f,4.f};

struct Ptr4 { const float* p[4]; };

// ---------------- utility kernels ----------------
__global__ void copy_uv_kernel(const float* __restrict__ lu, const float* __restrict__ lv,
                               float* __restrict__ o1, float* __restrict__ o2) {
    int i = blockIdx.x * blockDim.x + threadIdx.x;
    if (i < NH*NTOK) { o1[i] = lu[i]; o2[i] = lv[i]; }
}

__global__ void ln_kernel(const float* __restrict__ in, const float* __restrict__ g,
                          const float* __restrict__ b, float* __restrict__ out) {
    int row = blockIdx.x;
    int t = threadIdx.x;
    const float* x = in + (size_t)row * DMOD;
    float v0 = x[t], v1 = x[t + 256];
    __shared__ float red[256];
    red[t] = v0 + v1;
    __syncthreads();
    for (int o = 128; o > 0; o >>= 1) { if (t < o) red[t] += red[t + o]; __syncthreads(); }
    float mean = red[0] * (1.f / DMOD);
    __syncthreads();
    float d0 = v0 - mean, d1 = v1 - mean;
    red[t] = d0 * d0 + d1 * d1;
    __syncthreads();
    for (int o = 128; o > 0; o >>= 1) { if (t < o) red[t] += red[t + o]; __syncthreads(); }
    float r = rsqrtf(red[0] * (1.f / DMOD) + 1e-5f);
    out[(size_t)row * DMOD + t]       = d0 * r * g[t]       + b[t];
    out[(size_t)row * DMOD + t + 256] = d1 * r * g[t + 256] + b[t + 256];
}

__global__ void qkln_kernel(float* __restrict__ base) {
    int gidx = blockIdx.x * 8 + (threadIdx.x >> 5);
    int lane = threadIdx.x & 31;
    if (gidx >= NTOK * NH) return;
    int n = gidx / NH, h = gidx % NH;
    float* p = base + (size_t)n * (4*DMOD) + blockIdx.y * DMOD + h * DH;
    float v = p[lane];
    float s = v;
    for (int o = 16; o; o >>= 1) s += __shfl_xor_sync(0xffffffffu, s, o);
    float mean = s * (1.f / 32.f);
    float d = v - mean;
    float s2 = d * d;
    for (int o = 16; o; o >>= 1) s2 += __shfl_xor_sync(0xffffffffu, s2, o);
    p[lane] = d * rsqrtf(s2 * (1.f / 32.f) + 1e-5f);
}

// ---------------- tensor-core helpers ----------------
__device__ __forceinline__ unsigned f2tf32(float f) {
    unsigned u;
    asm("cvt.rna.tf32.f32 %0, %1;" : "=r"(u) : "f"(f));
    return u;
}

__device__ __forceinline__ void mma_tf32(float c[4], const unsigned a[4], const unsigned b[2]) {
    asm volatile("mma.sync.aligned.m16n8k8.row.col.f32.tf32.tf32.f32 "
        "{%0,%1,%2,%3}, {%4,%5,%6,%7}, {%8,%9}, {%0,%1,%2,%3};"
        : "+f"(c[0]), "+f"(c[1]), "+f"(c[2]), "+f"(c[3])
        : "r"(a[0]), "r"(a[1]), "r"(a[2]), "r"(a[3]), "r"(b[0]), "r"(b[1]));
}

__device__ __forceinline__ void mma_bf16(float c[4], const unsigned a[4], const unsigned b[2]) {
    asm volatile("mma.sync.aligned.m16n8k16.row.col.f32.bf16.bf16.f32 "
        "{%0,%1,%2,%3}, {%4,%5,%6,%7}, {%8,%9}, {%0,%1,%2,%3};"
        : "+f"(c[0]), "+f"(c[1]), "+f"(c[2]), "+f"(c[3])
        : "r"(a[0]), "r"(a[1]), "r"(a[2]), "r"(a[3]), "r"(b[0]), "r"(b[1]));
}

__global__ void tc_gemm(const float* __restrict__ A, Ptr4 B4, float* __restrict__ C,
                        int Nn, int K, int colsPer, int KC) {
    __shared__ float As[32][136];
    __shared__ float Bs[32][72];
    int tid = threadIdx.x;
    int m0 = blockIdx.y * 128, n0 = blockIdx.x * 64;
    const float* B = B4.p[n0 / colsPer] + (size_t)(n0 % colsPer) * K;
    int kbeg = blockIdx.z * KC, kend = kbeg + KC;

    int arow = tid >> 1, akseg = (tid & 1) << 4;
    int brow = tid & 63, bkseg = (tid >> 6) << 3;
    const float* Ap = A + (size_t)(m0 + arow) * K + akseg;
    const float* Bp = B + (size_t)brow * K + bkseg;

    int lane = tid & 31, g = lane >> 2, t = lane & 3;
    int wm = tid >> 6;
    int wn = (tid >> 5) & 1;
    int mBase = wm * 32, nBase = wn * 32;

    float c[2][4][4];
#pragma unroll
    for (int mi = 0; mi < 2; mi++)
#pragma unroll
        for (int ni = 0; ni < 4; ni++)
#pragma unroll
            for (int r = 0; r < 4; r++) c[mi][ni][r] = 0.f;

    for (int k0 = kbeg; k0 < kend; k0 += 32) {
        __syncthreads();
#pragma unroll
        for (int i = 0; i < 4; i++) {
            float4 a4 = *(const float4*)(Ap + k0 + 4 * i);
            As[akseg + 4*i + 0][arow] = __uint_as_float(f2tf32(a4.x));
            As[akseg + 4*i + 1][arow] = __uint_as_float(f2tf32(a4.y));
            As[akseg + 4*i + 2][arow] = __uint_as_float(f2tf32(a4.z));
            As[akseg + 4*i + 3][arow] = __uint_as_float(f2tf32(a4.w));
        }
#pragma unroll
        for (int i = 0; i < 2; i++) {
            float4 b4 = *(const float4*)(Bp + k0 + 4 * i);
            Bs[bkseg + 4*i + 0][brow] = __uint_as_float(f2tf32(b4.x));
            Bs[bkseg + 4*i + 1][brow] = __uint_as_float(f2tf32(b4.y));
            Bs[bkseg + 4*i + 2][brow] = __uint_as_float(f2tf32(b4.z));
            Bs[bkseg + 4*i + 3][brow] = __uint_as_float(f2tf32(b4.w));
        }
        __syncthreads();
#pragma unroll
        for (int ks = 0; ks < 32; ks += 8) {
            unsigned a[2][4], b[4][2];
#pragma unroll
            for (int mi = 0; mi < 2; mi++) {
                int mo = mBase + mi * 16 + g;
                a[mi][0] = __float_as_uint(As[ks + t][mo]);
                a[mi][1] = __float_as_uint(As[ks + t][mo + 8]);
                a[mi][2] = __float_as_uint(As[ks + t + 4][mo]);
                a[mi][3] = __float_as_uint(As[ks + t + 4][mo + 8]);
            }
#pragma unroll
            for (int ni = 0; ni < 4; ni++) {
                int no = nBase + ni * 8 + g;
                b[ni][0] = __float_as_uint(Bs[ks + t][no]);
                b[ni][1] = __float_as_uint(Bs[ks + t + 4][no]);
            }
#pragma unroll
            for (int mi = 0; mi < 2; mi++)
#pragma unroll
                for (int ni = 0; ni < 4; ni++)
                    mma_tf32(c[mi][ni], a[mi], b[ni]);
        }
    }

    float* Co = C + (size_t)blockIdx.z * NTOK * Nn;
#pragma unroll
    for (int mi = 0; mi < 2; mi++) {
        int r0 = m0 + mBase + mi * 16 + g;
#pragma unroll
        for (int ni = 0; ni < 4; ni++) {
            int col = n0 + nBase + ni * 8 + 2 * t;
            *(float2*)(Co + (size_t)r0 * Nn + col)       = make_float2(c[mi][ni][0], c[mi][ni][1]);
            *(float2*)(Co + (size_t)(r0 + 8) * Nn + col) = make_float2(c[mi][ni][2], c[mi][ni][3]);
        }
    }
}

__global__ void reduce_add(const float* __restrict__ R, const float* __restrict__ part,
                           int Z, float* __restrict__ out, int n) {
    int i = blockIdx.x * 256 + threadIdx.x;
    if (i >= n) return;
    float a = R[i];
    for (int z = 0; z < Z; z++) a += part[(size_t)z * n + i];
    out[i] = a;
}

// ---------------- build EK = exp(logK) in bf16 ----------------
__global__ void build_logk(const float* __restrict__ wrel, const float* __restrict__ xres,
                           const float* __restrict__ wdist) {
    __shared__ float Qs[32][68];
    __shared__ float Ks[32][68];
    __shared__ float xa[64][3], xb[64][3];
    int h = blockIdx.z;
    int n0 = blockIdx.y * 64, m0 = blockIdx.x * 64;
    int t = threadIdx.x;

    {
        int r = t >> 2, seg = (t & 3) << 3;
        const float* qp = g_qkvg + (size_t)(n0 + r) * (4*DMOD) + h * DH + seg;
        const float* kp = g_qkvg + (size_t)(m0 + r) * (4*DMOD) + DMOD + h * DH + seg;
#pragma unroll
        for (int i = 0; i < 2; i++) {
            float4 q4 = *(const float4*)(qp + 4*i);
            float4 k4 = *(const float4*)(kp + 4*i);
            Qs[seg + 4*i + 0][r] = q4.x; Qs[seg + 4*i + 1][r] = q4.y;
            Qs[seg + 4*i + 2][r] = q4.z; Qs[seg + 4*i + 3][r] = q4.w;
            Ks[seg + 4*i + 0][r] = k4.x; Ks[seg + 4*i + 1][r] = k4.y;
            Ks[seg + 4*i + 2][r] = k4.z; Ks[seg + 4*i + 3][r] = k4.w;
        }
    }
    if (t < 192) { int r = t / 3, c = t % 3; xa[r][c] = xres[(n0 + r) * 3 + c]; }
    if (t >= 64 && t < 256) {
        int u = t - 64;
        if (u < 192) { int r = u / 3, c = u % 3; xb[r][c] = xres[(m0 + r) * 3 + c]; }
    }
    __syncthreads();

    int tm = t >> 4, tn = t & 15;
    float acc[4][4] = {};
#pragma unroll
    for (int k = 0; k < 32; k++) {
        float4 av = *(const float4*)&Qs[k][tm << 2];
        float4 bv = *(const float4*)&Ks[k][tn << 2];
        float a[4] = {av.x, av.y, av.z, av.w};
        float bb[4] = {bv.x, bv.y, bv.z, bv.w};
#pragma unroll
        for (int i = 0; i < 4; i++)
#pragma unroll
            for (int j = 0; j < 4; j++) acc[i][j] += a[i] * bb[j];
    }

    float inve = 1.f / c_eps[h];
    float wd = wdist[h] * 0.01f;
    const float scale = 0.17677669529663687f;
#pragma unroll
    for (int i = 0; i < 4; i++) {
        int nl = (tm << 2) + i;
        int n = n0 + nl;
        float ax0 = xa[nl][0], ax1 = xa[nl][1], ax2 = xa[nl][2];
        size_t base = ((size_t)h * NTOK + n) * NTOK + m0 + (tn << 2);
        float4 w4 = *(const float4*)(wrel + base);
        float e[4];
#pragma unroll
        for (int j = 0; j < 4; j++) {
            int ml = (tn << 2) + j;
            float dx = ax0 - xb[ml][0];
            float dy = ax1 - xb[ml][1];
            float dz = ax2 - xb[ml][2];
            float d2 = dx * dx + dy * dy + dz * dz;
            float wr = (j == 0) ? w4.x : (j == 1) ? w4.y : (j == 2) ? w4.z : w4.w;
            e[j] = __expf((acc[i][j] * scale + wr - wd * d2) * inve);
        }
        *(__nv_bfloat162*)(g_EK + base)     = __floats2bfloat162_rn(e[0], e[1]);
        *(__nv_bfloat162*)(g_EK + base + 2) = __floats2bfloat162_rn(e[2], e[3]);
    }
}

// ---------------- Sinkhorn iteration via tensor cores ----------------
// Block = 16 rows x 1280 cols of one head. Row pass: S = EK@ev (B = ev replicated).
// Col pass: T_partial = eu^T @ EK (A row0 = eu, B = EK via ldmatrix.trans).
// grid (NSTRIPE=80, NH), 256 threads (8 warps).
__global__ void sink_mma(const float* __restrict__ mu, int it) {
    __shared__ __align__(16) __nv_bfloat16 tile[16 * TW];  // 41.2 KB
    __shared__ unsigned evu[640];   // packed bf16x2 of ev
    __shared__ float rowpart[8][16];
    __shared__ float eusm[16];
    __shared__ unsigned euu[8];     // packed bf16x2 of eu (16 rows)
    int h = blockIdx.y, stripe = blockIdx.x;
    int tid = threadIdx.x, warp = tid >> 5, lane = tid & 31;
    int g = lane >> 2, t = lane & 3;
    int row0 = stripe * 16;

    // async tile load: 16 rows x 1280 halves
    {
        const __nv_bfloat16* gsrc = g_EK + ((size_t)h * NTOK + row0) * NTOK;
#pragma unroll
        for (int k = 0; k < 10; k++) {
            int idx = tid + k * 256;
            int r = idx / 160, c16 = idx % 160;
            unsigned saddr = (unsigned)__cvta_generic_to_shared(tile + r * TW + c16 * 8);
            const void* gaddr = (const void*)(gsrc + (size_t)r * NTOK + c16 * 8);
            asm volatile("cp.async.cg.shared.global [%0], [%1], 16;\n" :: "r"(saddr), "l"(gaddr));
        }
        asm volatile("cp.async.commit_group;\n");
    }

    // prologue: ev packed bf16
    if (it == 0) {
        for (int i = tid; i < 640; i += 256) evu[i] = 0x3F803F80u;  // {1.0bf, 1.0bf}
    } else {
        const float* evp = g_ev + h * NTOK;
        for (int i = tid; i < 640; i += 256) {
            float2 e = *(const float2*)(evp + 2 * i);
            __nv_bfloat162 p = __floats2bfloat162_rn(e.x, e.y);
            evu[i] = *(unsigned*)&p;
        }
    }
    asm volatile("cp.async.wait_group 0;\n");
    __syncthreads();

    unsigned base = (unsigned)__cvta_generic_to_shared(tile);
    // ---- row pass: warp w covers k in [w*160, (w+1)*160), 10 chunks of 16
    {
        float c[4] = {0.f, 0.f, 0.f, 0.f};
        int rr = (lane & 7) + ((lane >> 3) & 1) * 8;   // row within tile for ldmatrix.x4
        int kh = (lane >> 4) * 8;                      // k-half offset (halves)
#pragma unroll
        for (int j = 0; j < 10; j++) {
            int kc = (warp * 10 + j) * 16;
            unsigned addr = base + (unsigned)((rr * TW + kc + kh) * 2);
            unsigned a[4];
            asm volatile("ldmatrix.sync.aligned.m8n8.x4.shared.b16 {%0,%1,%2,%3}, [%4];"
                : "=r"(a[0]), "=r"(a[1]), "=r"(a[2]), "=r"(a[3]) : "r"(addr));
            unsigned b[2];
            b[0] = evu[kc / 2 + t];
            b[1] = evu[kc / 2 + 4 + t];
            mma_bf16(c, a, b);
        }
        if (t == 0) {
            rowpart[warp][g] = c[0];
            rowpart[warp][g + 8] = c[2];
        }
    }
    __syncthreads();
    float fi = 1.f / (1.f + c_eps[h]);
    if (tid < 16) {
        float S = rowpart[0][tid];
#pragma unroll
        for (int w = 1; w < 8; w++) S += rowpart[w][tid];
        float lu = fi * (__logf(fmaxf(mu[h * NTOK + row0 + tid], 1e-8f)) - __logf(S));
        float eu = __expf(lu);
        g_lu[h * NTOK + row0 + tid] = lu;
        g_eu[h * NTOK + row0 + tid] = eu;
        eusm[tid] = eu;
    }
    __syncthreads();
    if (tid < 8) {
        __nv_bfloat162 p = __floats2bfloat162_rn(eusm[2 * tid], eusm[2 * tid + 1]);
        euu[tid] = *(unsigned*)&p;
    }
    __syncthreads();

    // ---- col pass: warp w covers n-tiles [w*20, (w+1)*20)
    {
        unsigned a[4];
        a[0] = (g == 0) ? euu[t] : 0u;
        a[1] = 0u;
        a[2] = (g == 0) ? euu[4 + t] : 0u;
        a[3] = 0u;
        float* outp = g_cpart + ((size_t)h * NSTRIPE + stripe) * NTOK;
        int rl = lane & 15;
#pragma unroll
        for (int j = 0; j < 20; j++) {
            int n0 = (warp * 20 + j) * 8;
            unsigned addr = base + (unsigned)((rl * TW + n0) * 2);
            unsigned b[2];
            asm volatile("ldmatrix.sync.aligned.m8n8.x2.trans.shared.b16 {%0,%1}, [%2];"
                : "=r"(b[0]), "=r"(b[1]) : "r"(addr));
            float d[4] = {0.f, 0.f, 0.f, 0.f};
            mma_bf16(d, a, b);
            if (g == 0) {
                outp[n0 + 2 * t]     = d[0];
                outp[n0 + 2 * t + 1] = d[1];
            }
        }
    }
}

// column finish: T_m = sum_stripes; lv = fi*(log(nu)-log(T)); ev = exp(lv)
__global__ void sink_colfin(const float* __restrict__ nu) {
    int i = blockIdx.x * 256 + threadIdx.x;
    if (i >= NH * NTOK) return;
    int h = i / NTOK;
    int m = i % NTOK;
    const float* p = g_cpart + (size_t)h * NSTRIPE * NTOK + m;
    float T = 0.f;
#pragma unroll 8
    for (int s = 0; s < NSTRIPE; s++) T += p[(size_t)s * NTOK];
    float fi = 1.f / (1.f + c_eps[h]);
    float lv = fi * (logf(fmaxf(nu[i], 1e-8f)) - logf(T));
    g_lv[i] = lv;
    g_ev[i] = __expf(lv);
}

// ---------------- build W^T = (diag(ev)[V | x | 1])^T in bf16 ----------------
__global__ void build_W(const float* __restrict__ xres) {
    __shared__ float Vs[256][33];
    __shared__ float evs[256];
    __shared__ float xs[256][3];
    int h = blockIdx.y;
    int m0 = blockIdx.x * 256;
    int tid = threadIdx.x;
    for (int i = tid; i < 256 * 32; i += 256) {
        int r = i >> 5, c = i & 31;
        Vs[r][c] = g_qkvg[(size_t)(m0 + r) * (4*DMOD) + 2*DMOD + h * DH + c];
    }
    evs[tid] = g_ev[h * NTOK + m0 + tid];
    xs[tid][0] = xres[(m0 + tid) * 3 + 0];
    xs[tid][1] = xres[(m0 + tid) * 3 + 1];
    xs[tid][2] = xres[(m0 + tid) * 3 + 2];
    __syncthreads();
    float e = evs[tid];
#pragma unroll
    for (int d = 0; d < WCOLS; d++) {
        float v;
        if (d < 32) v = e * Vs[tid][d];
        else if (d < 35) v = e * xs[tid][d - 32];
        else if (d == 35) v = e;
        else v = 0.f;
        g_Wt[((size_t)h * WCOLS + d) * NTOK + m0 + tid] = __float2bfloat16(v);
    }
}

// ---------------- papply via bf16 MMA: C = EK @ W, then scale by eu ----------------
__global__ void papply_mma(const float* __restrict__ xres) {
    __shared__ unsigned As_u[128 * 20];
    __shared__ unsigned Bs_u[WCOLS * 20];
    __shared__ float Cs[128 * 41];
    __shared__ float eus[128];
    int h = blockIdx.y;
    int n0 = blockIdx.x * 128;
    int tid = threadIdx.x;
    int warp = tid >> 5, lane = tid & 31;
    int g = lane >> 2, t = lane & 3;

    if (tid < 128) eus[tid] = g_eu[h * NTOK + n0 + tid];

    float c[5][4];
#pragma unroll
    for (int nt = 0; nt < 5; nt++)
#pragma unroll
        for (int r = 0; r < 4; r++) c[nt][r] = 0.f;

    int arow = tid >> 1, aq = (tid & 1) * 2;
    for (int k0 = 0; k0 < NTOK; k0 += 32) {
        __syncthreads();
        {
            const uint4* src = (const uint4*)(g_EK + ((size_t)h * NTOK + n0 + arow) * NTOK + k0);
#pragma unroll
            for (int j = 0; j < 2; j++) {
                *(uint4*)(As_u + arow * 20 + (aq + j) * 4) = src[aq + j];
            }
        }
        if (tid < 160) {
            int d = tid >> 2, q = tid & 3;
            const uint4* src = (const uint4*)(g_Wt + ((size_t)h * WCOLS + d) * NTOK + k0);
            *(uint4*)(Bs_u + d * 20 + q * 4) = src[q];
        }
        __syncthreads();
#pragma unroll
        for (int ks2 = 0; ks2 < 16; ks2 += 8) {
            const unsigned* au = As_u + (warp * 16 + g) * 20;
            const unsigned* au8 = au + 8 * 20;
            unsigned a[4];
            a[0] = au[ks2 + t];
            a[1] = au8[ks2 + t];
            a[2] = au[ks2 + t + 4];
            a[3] = au8[ks2 + t + 4];
#pragma unroll
            for (int nt = 0; nt < 5; nt++) {
                const unsigned* bu = Bs_u + (nt * 8 + g) * 20;
                unsigned b[2];
                b[0] = bu[ks2 + t];
                b[1] = bu[ks2 + t + 4];
                mma_bf16(c[nt], a, b);
            }
        }
    }

#pragma unroll
    for (int nt = 0; nt < 5; nt++) {
        int row = warp * 16 + g;
        int col = nt * 8 + 2 * t;
        Cs[row * 41 + col]     = c[nt][0];
        Cs[row * 41 + col + 1] = c[nt][1];
        Cs[(row + 8) * 41 + col]     = c[nt][2];
        Cs[(row + 8) * 41 + col + 1] = c[nt][3];
    }
    __syncthreads();

    for (int i = tid; i < 128 * 32; i += 256) {
        int r = i >> 5, d = i & 31;
        int n = n0 + r;
        float attn = eus[r] * Cs[r * 41 + d];
        float gt = g_qkvg[(size_t)n * (4*DMOD) + 3*DMOD + h * DH + d];
        g_o[(size_t)n * DMOD + h * DH + d] = attn / (1.f + __expf(-gt));
    }
    for (int r = tid; r < 128; r += 256) {
        int n = n0 + r;
        float e = eus[r];
        g_xc[((size_t)h * NTOK + n) * 3 + 0] = e * Cs[r * 41 + 32];
        g_xc[((size_t)h * NTOK + n) * 3 + 1] = e * Cs[r * 41 + 33];
        g_xc[((size_t)h * NTOK + n) * 3 + 2] = e * Cs[r * 41 + 34];
        g_rows[h * NTOK + n] = e * Cs[r * 41 + 35];
    }
}

__global__ void xout_kernel(const float* __restrict__ xres, const float* __restrict__ gamma,
                            float* __restrict__ out) {
    int n = blockIdx.x * 256 + threadIdx.x;
    if (n >= NTOK) return;
    float x0 = xres[n * 3 + 0], x1 = xres[n * 3 + 1], x2 = xres[n * 3 + 2];
    float a0 = 0.f, a1 = 0.f, a2 = 0.f;
    for (int h = 0; h < NH; h++) {
        float r = 1.f / (g_rows[h * NTOK + n] + 1e-8f);
        float gm = gamma[h];
        a0 += gm * (x0 - g_xc[((size_t)h * NTOK + n) * 3 + 0] * r);
        a1 += gm * (x1 - g_xc[((size_t)h * NTOK + n) * 3 + 1] * r);
        a2 += gm * (x2 - g_xc[((size_t)h * NTOK + n) * 3 + 2] * r);
    }
    out[n * 3 + 0] = x0 + a0;
    out[n * 3 + 1] = x1 + a1;
    out[n * 3 + 2] = x2 + a2;
}

__global__ void silumul_kernel() {
    int i = blockIdx.x * 256 + threadIdx.x;
    if (i < NTOK * DFF) {
        int n = i >> 11, j = i & (DFF - 1);
        float a = g_t12[(size_t)n * (2*DFF) + j];
        float b = g_t12[(size_t)n * (2*DFF) + DFF + j];
        g_t1[i] = a / (1.f + __expf(-a)) * b;
    }
}

// ---------------- launch ----------------
extern "C" void kernel_launch(void* const* d_in, const int* in_sizes, int n_in,
                              void* d_out, int out_size) {
    const float* h_in  = (const float*)d_in[0];
    const float* x_res = (const float*)d_in[1];
    const float* mu    = (const float*)d_in[2];
    const float* nu    = (const float*)d_in[3];
    const float* wrel  = (const float*)d_in[4];
    const float* wdist = (const float*)d_in[5];
    const float* ln_ag = (const float*)d_in[7];
    const float* ln_ab = (const float*)d_in[8];
    const float* Wq    = (const float*)d_in[9];
    const float* Wk    = (const float*)d_in[10];
    const float* Wv    = (const float*)d_in[11];
    const float* Wg    = (const float*)d_in[12];
    const float* Wo    = (const float*)d_in[13];
    const float* gamma = (const float*)d_in[14];
    const float* ln_fg = (const float*)d_in[15];
    const float* ln_fb = (const float*)d_in[16];
    const float* W1    = (const float*)d_in[17];
    const float* W2    = (const float*)d_in[18];
    const float* W3    = (const float*)d_in[19];
    float* out = (float*)d_out;

    float *p_hn, *p_qkvg, *p_lu, *p_lv, *p_o, *p_h2, *p_hf, *p_t1, *p_part, *p_t12;
    cudaGetSymbolAddress((void**)&p_hn,     g_hn);
    cudaGetSymbolAddress((void**)&p_qkvg,   g_qkvg);
    cudaGetSymbolAddress((void**)&p_lu,     g_lu);
    cudaGetSymbolAddress((void**)&p_lv,     g_lv);
    cudaGetSymbolAddress((void**)&p_o,      g_o);
    cudaGetSymbolAddress((void**)&p_h2,     g_h2);
    cudaGetSymbolAddress((void**)&p_hf,     g_hf);
    cudaGetSymbolAddress((void**)&p_t1,     g_t1);
    cudaGetSymbolAddress((void**)&p_part,   g_part);
    cudaGetSymbolAddress((void**)&p_t12,    g_t12);

    const int OUT_X  = NTOK * DMOD;
    const int OUT_LU = OUT_X + NTOK * 3;
    const int OUT_LV = OUT_LU + NH * NTOK;

    ln_kernel<<<NTOK, 256>>>(h_in, ln_ag, ln_ab, p_hn);

    Ptr4 bqkvg; bqkvg.p[0] = Wq; bqkvg.p[1] = Wk; bqkvg.p[2] = Wv; bqkvg.p[3] = Wg;
    tc_gemm<<<dim3(4*DMOD/64, NTOK/128, 1), 256>>>(p_hn, bqkvg, p_qkvg, 4*DMOD, DMOD, DMOD, DMOD);

    qkln_kernel<<<dim3((NTOK * NH) / 8, 2), 256>>>(p_qkvg);

    build_logk<<<dim3(NTOK / 64, NTOK / 64, NH), 256>>>(wrel, x_res, wdist);

    dim3 gsink(NSTRIPE, NH);
    for (int it = 0; it < NITER; it++) {
        sink_mma<<<gsink, 256>>>(mu, it);
        sink_colfin<<<(NH * NTOK + 255) / 256, 256>>>(nu);
    }

    build_W<<<dim3(NTOK / 256, NH), 256>>>(x_res);
    papply_mma<<<dim3(NTOK / 128, NH), 256>>>(x_res);

    Ptr4 bWo; bWo.p[0] = Wo; bWo.p[1] = Wo; bWo.p[2] = Wo; bWo.p[3] = Wo;
    tc_gemm<<<dim3(DMOD/64, NTOK/128, 2), 256>>>(p_o, bWo, p_part, DMOD, DMOD, DMOD, DMOD/2);
    reduce_add<<<(NTOK*DMOD)/256, 256>>>(h_in, p_part, 2, p_h2, NTOK*DMOD);

    xout_kernel<<<(NTOK + 255) / 256, 256>>>(x_res, gamma, out + OUT_X);

    ln_kernel<<<NTOK, 256>>>(p_h2, ln_fg, ln_fb, p_hf);
    Ptr4 b12; b12.p[0] = W1; b12.p[1] = W2; b12.p[2] = W1; b12.p[3] = W1;
    tc_gemm<<<dim3(2*DFF/64, NTOK/128, 1), 256>>>(p_hf, b12, p_t12, 2*DFF, DMOD, DFF, DMOD);
    silumul_kernel<<<(NTOK * DFF) / 256, 256>>>();
    Ptr4 bW3; bW3.p[0] = W3; bW3.p[1] = W3; bW3.p[2] = W3; bW3.p[3] = W3;
    tc_gemm<<<dim3(DMOD/64, NTOK/128, 4), 256>>>(p_t1, bW3, p_part, DMOD, DFF, DMOD, DFF/4);
    reduce_add<<<(NTOK*DMOD)/256, 256>>>(p_h2, p_part, 4, out, NTOK*DMOD);

    copy_uv_kernel<<<(NH * NTOK + 1023) / 1024, 1024>>>(p_lu, p_lv, out + OUT_LU, out + OUT_LV);
}

// round 12
// speedup vs baseline: 1.0310x; 1.0310x over previous
#include <cuda_runtime.h>
#include <cuda_fp16.h>
#include <cuda_bf16.h>
#include <math.h>

#define NTOK 1280
#define DMOD 512
#define NH   16
#define DH   32
#define DFF  2048
#define NITER 20
#define NSTRIPE 80           // sinkhorn stripes (16 rows each)
#define WCOLS 40             // W: 32 V + 3 x + 1 ones + 4 pad
#define TW 1288              // smem tile row stride in halves (1280 + 8 pad)

// ---------------- scratch ----------------
__device__ __nv_bfloat16 g_EK[NH*NTOK*NTOK];  // exp(logK), bf16
__device__ __nv_bfloat16 g_Wt[NH*WCOLS*NTOK]; // W^T per head: [d][m]
__device__ float g_cpart[NH*NSTRIPE*NTOK];    // sinkhorn col partials
__device__ float g_hn  [NTOK*DMOD];
__device__ float g_qkvg[NTOK*4*DMOD];         // [q | k | v | gate]
__device__ float g_lu [NH*NTOK];
__device__ float g_lv [NH*NTOK];
__device__ float g_eu [NH*NTOK];
__device__ float g_ev [NH*NTOK];
__device__ float g_xc [NH*NTOK*3];
__device__ float g_rows[NH*NTOK];
__device__ float g_o  [NTOK*DMOD];
__device__ float g_h2 [NTOK*DMOD];
__device__ float g_hf [NTOK*DMOD];
__device__ float g_t12[NTOK*2*DFF];
__device__ float g_t1 [NTOK*DFF];
__device__ float g_part[4*NTOK*DMOD];         // split-K GEMM partials

__constant__ float c_eps[NH] = {0.5f,0.5f,0.5f,0.5f, 1.f,1.f,1.f,1.f,
                                2.f,2.f,2.f,2.f, 4.f,4.f,4.f,4.f};

struct Ptr4 { const float* p[4]; };

// ---------------- utility kernels ----------------
__global__ void copy_uv_kernel(const float* __restrict__ lu, const float* __restrict__ lv,
                               float* __restrict__ o1, float* __restrict__ o2) {
    int i = blockIdx.x * blockDim.x + threadIdx.x;
    if (i < NH*NTOK) { o1[i] = lu[i]; o2[i] = lv[i]; }
}

__global__ void ln_kernel(const float* __restrict__ in, const float* __restrict__ g,
                          const float* __restrict__ b, float* __restrict__ out) {
    int row = blockIdx.x;
    int t = threadIdx.x;
    const float* x = in + (size_t)row * DMOD;
    float v0 = x[t], v1 = x[t + 256];
    __shared__ float red[256];
    red[t] = v0 + v1;
    __syncthreads();
    for (int o = 128; o > 0; o >>= 1) { if (t < o) red[t] += red[t + o]; __syncthreads(); }
    float mean = red[0] * (1.f / DMOD);
    __syncthreads();
    float d0 = v0 - mean, d1 = v1 - mean;
    red[t] = d0 * d0 + d1 * d1;
    __syncthreads();
    for (int o = 128; o > 0; o >>= 1) { if (t < o) red[t] += red[t + o]; __syncthreads(); }
    float r = rsqrtf(red[0] * (1.f / DMOD) + 1e-5f);
    out[(size_t)row * DMOD + t]       = d0 * r * g[t]       + b[t];
    out[(size_t)row * DMOD + t + 256] = d1 * r * g[t + 256] + b[t + 256];
}

__global__ void qkln_kernel(float* __restrict__ base) {
    int gidx = blockIdx.x * 8 + (threadIdx.x >> 5);
    int lane = threadIdx.x & 31;
    if (gidx >= NTOK * NH) return;
    int n = gidx / NH, h = gidx % NH;
    float* p = base + (size_t)n * (4*DMOD) + blockIdx.y * DMOD + h * DH;
    float v = p[lane];
    float s = v;
    for (int o = 16; o; o >>= 1) s += __shfl_xor_sync(0xffffffffu, s, o);
    float mean = s * (1.f / 32.f);
    float d = v - mean;
    float s2 = d * d;
    for (int o = 16; o; o >>= 1) s2 += __shfl_xor_sync(0xffffffffu, s2, o);
    p[lane] = d * rsqrtf(s2 * (1.f / 32.f) + 1e-5f);
}

// ---------------- tensor-core helpers ----------------
__device__ __forceinline__ unsigned f2tf32(float f) {
    unsigned u;
    asm("cvt.rna.tf32.f32 %0, %1;" : "=r"(u) : "f"(f));
    return u;
}

__device__ __forceinline__ void mma_tf32(float c[4], const unsigned a[4], const unsigned b[2]) {
    asm volatile("mma.sync.aligned.m16n8k8.row.col.f32.tf32.tf32.f32 "
        "{%0,%1,%2,%3}, {%4,%5,%6,%7}, {%8,%9}, {%0,%1,%2,%3};"
        : "+f"(c[0]), "+f"(c[1]), "+f"(c[2]), "+f"(c[3])
        : "r"(a[0]), "r"(a[1]), "r"(a[2]), "r"(a[3]), "r"(b[0]), "r"(b[1]));
}

__device__ __forceinline__ void mma_bf16(float c[4], const unsigned a[4], const unsigned b[2]) {
    asm volatile("mma.sync.aligned.m16n8k16.row.col.f32.bf16.bf16.f32 "
        "{%0,%1,%2,%3}, {%4,%5,%6,%7}, {%8,%9}, {%0,%1,%2,%3};"
        : "+f"(c[0]), "+f"(c[1]), "+f"(c[2]), "+f"(c[3])
        : "r"(a[0]), "r"(a[1]), "r"(a[2]), "r"(a[3]), "r"(b[0]), "r"(b[1]));
}

__global__ void tc_gemm(const float* __restrict__ A, Ptr4 B4, float* __restrict__ C,
                        int Nn, int K, int colsPer, int KC) {
    __shared__ float As[32][136];
    __shared__ float Bs[32][72];
    int tid = threadIdx.x;
    int m0 = blockIdx.y * 128, n0 = blockIdx.x * 64;
    const float* B = B4.p[n0 / colsPer] + (size_t)(n0 % colsPer) * K;
    int kbeg = blockIdx.z * KC, kend = kbeg + KC;

    int arow = tid >> 1, akseg = (tid & 1) << 4;
    int brow = tid & 63, bkseg = (tid >> 6) << 3;
    const float* Ap = A + (size_t)(m0 + arow) * K + akseg;
    const float* Bp = B + (size_t)brow * K + bkseg;

    int lane = tid & 31, g = lane >> 2, t = lane & 3;
    int wm = tid >> 6;
    int wn = (tid >> 5) & 1;
    int mBase = wm * 32, nBase = wn * 32;

    float c[2][4][4];
#pragma unroll
    for (int mi = 0; mi < 2; mi++)
#pragma unroll
        for (int ni = 0; ni < 4; ni++)
#pragma unroll
            for (int r = 0; r < 4; r++) c[mi][ni][r] = 0.f;

    for (int k0 = kbeg; k0 < kend; k0 += 32) {
        __syncthreads();
#pragma unroll
        for (int i = 0; i < 4; i++) {
            float4 a4 = *(const float4*)(Ap + k0 + 4 * i);
            As[akseg + 4*i + 0][arow] = __uint_as_float(f2tf32(a4.x));
            As[akseg + 4*i + 1][arow] = __uint_as_float(f2tf32(a4.y));
            As[akseg + 4*i + 2][arow] = __uint_as_float(f2tf32(a4.z));
            As[akseg + 4*i + 3][arow] = __uint_as_float(f2tf32(a4.w));
        }
#pragma unroll
        for (int i = 0; i < 2; i++) {
            float4 b4 = *(const float4*)(Bp + k0 + 4 * i);
            Bs[bkseg + 4*i + 0][brow] = __uint_as_float(f2tf32(b4.x));
            Bs[bkseg + 4*i + 1][brow] = __uint_as_float(f2tf32(b4.y));
            Bs[bkseg + 4*i + 2][brow] = __uint_as_float(f2tf32(b4.z));
            Bs[bkseg + 4*i + 3][brow] = __uint_as_float(f2tf32(b4.w));
        }
        __syncthreads();
#pragma unroll
        for (int ks = 0; ks < 32; ks += 8) {
            unsigned a[2][4], b[4][2];
#pragma unroll
            for (int mi = 0; mi < 2; mi++) {
                int mo = mBase + mi * 16 + g;
                a[mi][0] = __float_as_uint(As[ks + t][mo]);
                a[mi][1] = __float_as_uint(As[ks + t][mo + 8]);
                a[mi][2] = __float_as_uint(As[ks + t + 4][mo]);
                a[mi][3] = __float_as_uint(As[ks + t + 4][mo + 8]);
            }
#pragma unroll
            for (int ni = 0; ni < 4; ni++) {
                int no = nBase + ni * 8 + g;
                b[ni][0] = __float_as_uint(Bs[ks + t][no]);
                b[ni][1] = __float_as_uint(Bs[ks + t + 4][no]);
            }
#pragma unroll
            for (int mi = 0; mi < 2; mi++)
#pragma unroll
                for (int ni = 0; ni < 4; ni++)
                    mma_tf32(c[mi][ni], a[mi], b[ni]);
        }
    }

    float* Co = C + (size_t)blockIdx.z * NTOK * Nn;
#pragma unroll
    for (int mi = 0; mi < 2; mi++) {
        int r0 = m0 + mBase + mi * 16 + g;
#pragma unroll
        for (int ni = 0; ni < 4; ni++) {
            int col = n0 + nBase + ni * 8 + 2 * t;
            *(float2*)(Co + (size_t)r0 * Nn + col)       = make_float2(c[mi][ni][0], c[mi][ni][1]);
            *(float2*)(Co + (size_t)(r0 + 8) * Nn + col) = make_float2(c[mi][ni][2], c[mi][ni][3]);
        }
    }
}

__global__ void reduce_add(const float* __restrict__ R, const float* __restrict__ part,
                           int Z, float* __restrict__ out, int n) {
    int i = blockIdx.x * 256 + threadIdx.x;
    if (i >= n) return;
    float a = R[i];
    for (int z = 0; z < Z; z++) a += part[(size_t)z * n + i];
    out[i] = a;
}

// ---------------- build EK = exp(logK) in bf16 ----------------
__global__ void build_logk(const float* __restrict__ wrel, const float* __restrict__ xres,
                           const float* __restrict__ wdist) {
    __shared__ float Qs[32][68];
    __shared__ float Ks[32][68];
    __shared__ float xa[64][3], xb[64][3];
    int h = blockIdx.z;
    int n0 = blockIdx.y * 64, m0 = blockIdx.x * 64;
    int t = threadIdx.x;

    {
        int r = t >> 2, seg = (t & 3) << 3;
        const float* qp = g_qkvg + (size_t)(n0 + r) * (4*DMOD) + h * DH + seg;
        const float* kp = g_qkvg + (size_t)(m0 + r) * (4*DMOD) + DMOD + h * DH + seg;
#pragma unroll
        for (int i = 0; i < 2; i++) {
            float4 q4 = *(const float4*)(qp + 4*i);
            float4 k4 = *(const float4*)(kp + 4*i);
            Qs[seg + 4*i + 0][r] = q4.x; Qs[seg + 4*i + 1][r] = q4.y;
            Qs[seg + 4*i + 2][r] = q4.z; Qs[seg + 4*i + 3][r] = q4.w;
            Ks[seg + 4*i + 0][r] = k4.x; Ks[seg + 4*i + 1][r] = k4.y;
            Ks[seg + 4*i + 2][r] = k4.z; Ks[seg + 4*i + 3][r] = k4.w;
        }
    }
    if (t < 192) { int r = t / 3, c = t % 3; xa[r][c] = xres[(n0 + r) * 3 + c]; }
    if (t >= 64 && t < 256) {
        int u = t - 64;
        if (u < 192) { int r = u / 3, c = u % 3; xb[r][c] = xres[(m0 + r) * 3 + c]; }
    }
    __syncthreads();

    int tm = t >> 4, tn = t & 15;
    float acc[4][4] = {};
#pragma unroll
    for (int k = 0; k < 32; k++) {
        float4 av = *(const float4*)&Qs[k][tm << 2];
        float4 bv = *(const float4*)&Ks[k][tn << 2];
        float a[4] = {av.x, av.y, av.z, av.w};
        float bb[4] = {bv.x, bv.y, bv.z, bv.w};
#pragma unroll
        for (int i = 0; i < 4; i++)
#pragma unroll
            for (int j = 0; j < 4; j++) acc[i][j] += a[i] * bb[j];
    }

    float inve = 1.f / c_eps[h];
    float wd = wdist[h] * 0.01f;
    const float scale = 0.17677669529663687f;
#pragma unroll
    for (int i = 0; i < 4; i++) {
        int nl = (tm << 2) + i;
        int n = n0 + nl;
        float ax0 = xa[nl][0], ax1 = xa[nl][1], ax2 = xa[nl][2];
        size_t base = ((size_t)h * NTOK + n) * NTOK + m0 + (tn << 2);
        float4 w4 = *(const float4*)(wrel + base);
        float e[4];
#pragma unroll
        for (int j = 0; j < 4; j++) {
            int ml = (tn << 2) + j;
            float dx = ax0 - xb[ml][0];
            float dy = ax1 - xb[ml][1];
            float dz = ax2 - xb[ml][2];
            float d2 = dx * dx + dy * dy + dz * dz;
            float wr = (j == 0) ? w4.x : (j == 1) ? w4.y : (j == 2) ? w4.z : w4.w;
            e[j] = __expf((acc[i][j] * scale + wr - wd * d2) * inve);
        }
        *(__nv_bfloat162*)(g_EK + base)     = __floats2bfloat162_rn(e[0], e[1]);
        *(__nv_bfloat162*)(g_EK + base + 2) = __floats2bfloat162_rn(e[2], e[3]);
    }
}

// ---------------- Sinkhorn iteration via tensor cores + TMA bulk loads ----------------
// Block = 16 rows x 1280 cols of one head. Tile loaded with 16 cp.async.bulk (one per
// row, 2560 B each) into a padded smem tile (conflict-free ldmatrix), one mbarrier.
// Row pass: S = EK@ev (B = ev replicated). Col pass: T_partial = eu^T@EK (ldmatrix.trans).
__global__ void sink_mma(const float* __restrict__ mu, int it) {
    __shared__ __align__(16) __nv_bfloat16 tile[16 * TW];  // 41.2 KB
    __shared__ unsigned evu[640];   // packed bf16x2 of ev
    __shared__ float rowpart[8][16];
    __shared__ float eusm[16];
    __shared__ unsigned euu[8];     // packed bf16x2 of eu (16 rows)
    __shared__ __align__(8) unsigned long long mbar;
    int h = blockIdx.y, stripe = blockIdx.x;
    int tid = threadIdx.x, warp = tid >> 5, lane = tid & 31;
    int g = lane >> 2, t = lane & 3;
    int row0 = stripe * 16;

    unsigned mbar_a = (unsigned)__cvta_generic_to_shared(&mbar);
    if (tid == 0) {
        asm volatile("mbarrier.init.shared.b64 [%0], 1;" :: "r"(mbar_a) : "memory");
    }
    __syncthreads();

    // TMA bulk tile load: 16 rows, one 2560B bulk per row (padded smem stride)
    if (tid == 0) {
        asm volatile("mbarrier.arrive.expect_tx.shared.b64 _, [%0], %1;"
                     :: "r"(mbar_a), "r"(16u * NTOK * 2u) : "memory");
        const __nv_bfloat16* gsrc = g_EK + ((size_t)h * NTOK + row0) * NTOK;
#pragma unroll
        for (int r = 0; r < 16; r++) {
            unsigned saddr = (unsigned)__cvta_generic_to_shared(tile + r * TW);
            const void* gaddr = (const void*)(gsrc + (size_t)r * NTOK);
            asm volatile("cp.async.bulk.shared::cluster.global.mbarrier::complete_tx::bytes "
                         "[%0], [%1], %2, [%3];"
                         :: "r"(saddr), "l"(gaddr), "r"(NTOK * 2u), "r"(mbar_a) : "memory");
        }
    }

    // prologue (overlapped with bulk): ev packed bf16
    if (it == 0) {
        for (int i = tid; i < 640; i += 256) evu[i] = 0x3F803F80u;  // {1.0bf, 1.0bf}
    } else {
        const float* evp = g_ev + h * NTOK;
        for (int i = tid; i < 640; i += 256) {
            float2 e = *(const float2*)(evp + 2 * i);
            __nv_bfloat162 p = __floats2bfloat162_rn(e.x, e.y);
            evu[i] = *(unsigned*)&p;
        }
    }

    // wait for tile
    {
        unsigned done;
        do {
            asm volatile("{\n\t.reg .pred p;\n\t"
                         "mbarrier.try_wait.parity.shared.b64 p, [%1], 0;\n\t"
                         "selp.u32 %0, 1, 0, p;\n\t}"
                         : "=r"(done) : "r"(mbar_a) : "memory");
        } while (!done);
    }
    __syncthreads();

    unsigned base = (unsigned)__cvta_generic_to_shared(tile);
    // ---- row pass: warp w covers k in [w*160, (w+1)*160), 10 chunks of 16
    {
        float c[4] = {0.f, 0.f, 0.f, 0.f};
        int rr = (lane & 7) + ((lane >> 3) & 1) * 8;   // row within tile for ldmatrix.x4
        int kh = (lane >> 4) * 8;                      // k-half offset (halves)
#pragma unroll
        for (int j = 0; j < 10; j++) {
            int kc = (warp * 10 + j) * 16;
            unsigned addr = base + (unsigned)((rr * TW + kc + kh) * 2);
            unsigned a[4];
            asm volatile("ldmatrix.sync.aligned.m8n8.x4.shared.b16 {%0,%1,%2,%3}, [%4];"
                : "=r"(a[0]), "=r"(a[1]), "=r"(a[2]), "=r"(a[3]) : "r"(addr));
            unsigned b[2];
            b[0] = evu[kc / 2 + t];
            b[1] = evu[kc / 2 + 4 + t];
            mma_bf16(c, a, b);
        }
        if (t == 0) {
            rowpart[warp][g] = c[0];
            rowpart[warp][g + 8] = c[2];
        }
    }
    __syncthreads();
    float fi = 1.f / (1.f + c_eps[h]);
    if (tid < 16) {
        float S = rowpart[0][tid];
#pragma unroll
        for (int w = 1; w < 8; w++) S += rowpart[w][tid];
        float lu = fi * (__logf(fmaxf(mu[h * NTOK + row0 + tid], 1e-8f)) - __logf(S));
        float eu = __expf(lu);
        g_lu[h * NTOK + row0 + tid] = lu;
        g_eu[h * NTOK + row0 + tid] = eu;
        eusm[tid] = eu;
    }
    __syncthreads();
    if (tid < 8) {
        __nv_bfloat162 p = __floats2bfloat162_rn(eusm[2 * tid], eusm[2 * tid + 1]);
        euu[tid] = *(unsigned*)&p;
    }
    __syncthreads();

    // ---- col pass: warp w covers n-tiles [w*20, (w+1)*20)
    {
        unsigned a[4];
        a[0] = (g == 0) ? euu[t] : 0u;
        a[1] = 0u;
        a[2] = (g == 0) ? euu[4 + t] : 0u;
        a[3] = 0u;
        float* outp = g_cpart + ((size_t)h * NSTRIPE + stripe) * NTOK;
        int rl = lane & 15;
#pragma unroll
        for (int j = 0; j < 20; j++) {
            int n0 = (warp * 20 + j) * 8;
            unsigned addr = base + (unsigned)((rl * TW + n0) * 2);
            unsigned b[2];
            asm volatile("ldmatrix.sync.aligned.m8n8.x2.trans.shared.b16 {%0,%1}, [%2];"
                : "=r"(b[0]), "=r"(b[1]) : "r"(addr));
            float d[4] = {0.f, 0.f, 0.f, 0.f};
            mma_bf16(d, a, b);
            if (g == 0) {
                outp[n0 + 2 * t]     = d[0];
                outp[n0 + 2 * t + 1] = d[1];
            }
        }
    }
}

// column finish: T_m = sum_stripes; lv = fi*(log(nu)-log(T)); ev = exp(lv)
__global__ void sink_colfin(const float* __restrict__ nu) {
    int i = blockIdx.x * 256 + threadIdx.x;
    if (i >= NH * NTOK) return;
    int h = i / NTOK;
    int m = i % NTOK;
    const float* p = g_cpart + (size_t)h * NSTRIPE * NTOK + m;
    float T = 0.f;
#pragma unroll 8
    for (int s = 0; s < NSTRIPE; s++) T += p[(size_t)s * NTOK];
    float fi = 1.f / (1.f + c_eps[h]);
    float lv = fi * (logf(fmaxf(nu[i], 1e-8f)) - logf(T));
    g_lv[i] = lv;
    g_ev[i] = __expf(lv);
}

// ---------------- build W^T = (diag(ev)[V | x | 1])^T in bf16 ----------------
__global__ void build_W(const float* __restrict__ xres) {
    __shared__ float Vs[256][33];
    __shared__ float evs[256];
    __shared__ float xs[256][3];
    int h = blockIdx.y;
    int m0 = blockIdx.x * 256;
    int tid = threadIdx.x;
    for (int i = tid; i < 256 * 32; i += 256) {
        int r = i >> 5, c = i & 31;
        Vs[r][c] = g_qkvg[(size_t)(m0 + r) * (4*DMOD) + 2*DMOD + h * DH + c];
    }
    evs[tid] = g_ev[h * NTOK + m0 + tid];
    xs[tid][0] = xres[(m0 + tid) * 3 + 0];
    xs[tid][1] = xres[(m0 + tid) * 3 + 1];
    xs[tid][2] = xres[(m0 + tid) * 3 + 2];
    __syncthreads();
    float e = evs[tid];
#pragma unroll
    for (int d = 0; d < WCOLS; d++) {
        float v;
        if (d < 32) v = e * Vs[tid][d];
        else if (d < 35) v = e * xs[tid][d - 32];
        else if (d == 35) v = e;
        else v = 0.f;
        g_Wt[((size_t)h * WCOLS + d) * NTOK + m0 + tid] = __float2bfloat16(v);
    }
}

// ---------------- papply via bf16 MMA: C = EK @ W, then scale by eu ----------------
__global__ void papply_mma(const float* __restrict__ xres) {
    __shared__ unsigned As_u[128 * 20];
    __shared__ unsigned Bs_u[WCOLS * 20];
    __shared__ float Cs[128 * 41];
    __shared__ float eus[128];
    int h = blockIdx.y;
    int n0 = blockIdx.x * 128;
    int tid = threadIdx.x;
    int warp = tid >> 5, lane = tid & 31;
    int g = lane >> 2, t = lane & 3;

    if (tid < 128) eus[tid] = g_eu[h * NTOK + n0 + tid];

    float c[5][4];
#pragma unroll
    for (int nt = 0; nt < 5; nt++)
#pragma unroll
        for (int r = 0; r < 4; r++) c[nt][r] = 0.f;

    int arow = tid >> 1, aq = (tid & 1) * 2;
    for (int k0 = 0; k0 < NTOK; k0 += 32) {
        __syncthreads();
        {
            const uint4* src = (const uint4*)(g_EK + ((size_t)h * NTOK + n0 + arow) * NTOK + k0);
#pragma unroll
            for (int j = 0; j < 2; j++) {
                *(uint4*)(As_u + arow * 20 + (aq + j) * 4) = src[aq + j];
            }
        }
        if (tid < 160) {
            int d = tid >> 2, q = tid & 3;
            const uint4* src = (const uint4*)(g_Wt + ((size_t)h * WCOLS + d) * NTOK + k0);
            *(uint4*)(Bs_u + d * 20 + q * 4) = src[q];
        }
        __syncthreads();
#pragma unroll
        for (int ks2 = 0; ks2 < 16; ks2 += 8) {
            const unsigned* au = As_u + (warp * 16 + g) * 20;
            const unsigned* au8 = au + 8 * 20;
            unsigned a[4];
            a[0] = au[ks2 + t];
            a[1] = au8[ks2 + t];
            a[2] = au[ks2 + t + 4];
            a[3] = au8[ks2 + t + 4];
#pragma unroll
            for (int nt = 0; nt < 5; nt++) {
                const unsigned* bu = Bs_u + (nt * 8 + g) * 20;
                unsigned b[2];
                b[0] = bu[ks2 + t];
                b[1] = bu[ks2 + t + 4];
                mma_bf16(c[nt], a, b);
            }
        }
    }

#pragma unroll
    for (int nt = 0; nt < 5; nt++) {
        int row = warp * 16 + g;
        int col = nt * 8 + 2 * t;
        Cs[row * 41 + col]     = c[nt][0];
        Cs[row * 41 + col + 1] = c[nt][1];
        Cs[(row + 8) * 41 + col]     = c[nt][2];
        Cs[(row + 8) * 41 + col + 1] = c[nt][3];
    }
    __syncthreads();

    for (int i = tid; i < 128 * 32; i += 256) {
        int r = i >> 5, d = i & 31;
        int n = n0 + r;
        float attn = eus[r] * Cs[r * 41 + d];
        float gt = g_qkvg[(size_t)n * (4*DMOD) + 3*DMOD + h * DH + d];
        g_o[(size_t)n * DMOD + h * DH + d] = attn / (1.f + __expf(-gt));
    }
    for (int r = tid; r < 128; r += 256) {
        int n = n0 + r;
        float e = eus[r];
        g_xc[((size_t)h * NTOK + n) * 3 + 0] = e * Cs[r * 41 + 32];
        g_xc[((size_t)h * NTOK + n) * 3 + 1] = e * Cs[r * 41 + 33];
        g_xc[((size_t)h * NTOK + n) * 3 + 2] = e * Cs[r * 41 + 34];
        g_rows[h * NTOK + n] = e * Cs[r * 41 + 35];
    }
}

__global__ void xout_kernel(const float* __restrict__ xres, const float* __restrict__ gamma,
                            float* __restrict__ out) {
    int n = blockIdx.x * 256 + threadIdx.x;
    if (n >= NTOK) return;
    float x0 = xres[n * 3 + 0], x1 = xres[n * 3 + 1], x2 = xres[n * 3 + 2];
    float a0 = 0.f, a1 = 0.f, a2 = 0.f;
    for (int h = 0; h < NH; h++) {
        float r = 1.f / (g_rows[h * NTOK + n] + 1e-8f);
        float gm = gamma[h];
        a0 += gm * (x0 - g_xc[((size_t)h * NTOK + n) * 3 + 0] * r);
        a1 += gm * (x1 - g_xc[((size_t)h * NTOK + n) * 3 + 1] * r);
        a2 += gm * (x2 - g_xc[((size_t)h * NTOK + n) * 3 + 2] * r);
    }
    out[n * 3 + 0] = x0 + a0;
    out[n * 3 + 1] = x1 + a1;
    out[n * 3 + 2] = x2 + a2;
}

__global__ void silumul_kernel() {
    int i = blockIdx.x * 256 + threadIdx.x;
    if (i < NTOK * DFF) {
        int n = i >> 11, j = i & (DFF - 1);
        float a = g_t12[(size_t)n * (2*DFF) + j];
        float b = g_t12[(size_t)n * (2*DFF) + DFF + j];
        g_t1[i] = a / (1.f + __expf(-a)) * b;
    }
}

// ---------------- launch ----------------
extern "C" void kernel_launch(void* const* d_in, const int* in_sizes, int n_in,
                              void* d_out, int out_size) {
    const float* h_in  = (const float*)d_in[0];
    const float* x_res = (const float*)d_in[1];
    const float* mu    = (const float*)d_in[2];
    const float* nu    = (const float*)d_in[3];
    const float* wrel  = (const float*)d_in[4];
    const float* wdist = (const float*)d_in[5];
    const float* ln_ag = (const float*)d_in[7];
    const float* ln_ab = (const float*)d_in[8];
    const float* Wq    = (const float*)d_in[9];
    const float* Wk    = (const float*)d_in[10];
    const float* Wv    = (const float*)d_in[11];
    const float* Wg    = (const float*)d_in[12];
    const float* Wo    = (const float*)d_in[13];
    const float* gamma = (const float*)d_in[14];
    const float* ln_fg = (const float*)d_in[15];
    const float* ln_fb = (const float*)d_in[16];
    const float* W1    = (const float*)d_in[17];
    const float* W2    = (const float*)d_in[18];
    const float* W3    = (const float*)d_in[19];
    float* out = (float*)d_out;

    float *p_hn, *p_qkvg, *p_lu, *p_lv, *p_o, *p_h2, *p_hf, *p_t1, *p_part, *p_t12;
    cudaGetSymbolAddress((void**)&p_hn,     g_hn);
    cudaGetSymbolAddress((void**)&p_qkvg,   g_qkvg);
    cudaGetSymbolAddress((void**)&p_lu,     g_lu);
    cudaGetSymbolAddress((void**)&p_lv,     g_lv);
    cudaGetSymbolAddress((void**)&p_o,      g_o);
    cudaGetSymbolAddress((void**)&p_h2,     g_h2);
    cudaGetSymbolAddress((void**)&p_hf,     g_hf);
    cudaGetSymbolAddress((void**)&p_t1,     g_t1);
    cudaGetSymbolAddress((void**)&p_part,   g_part);
    cudaGetSymbolAddress((void**)&p_t12,    g_t12);

    const int OUT_X  = NTOK * DMOD;
    const int OUT_LU = OUT_X + NTOK * 3;
    const int OUT_LV = OUT_LU + NH * NTOK;

    ln_kernel<<<NTOK, 256>>>(h_in, ln_ag, ln_ab, p_hn);

    Ptr4 bqkvg; bqkvg.p[0] = Wq; bqkvg.p[1] = Wk; bqkvg.p[2] = Wv; bqkvg.p[3] = Wg;
    tc_gemm<<<dim3(4*DMOD/64, NTOK/128, 1), 256>>>(p_hn, bqkvg, p_qkvg, 4*DMOD, DMOD, DMOD, DMOD);

    qkln_kernel<<<dim3((NTOK * NH) / 8, 2), 256>>>(p_qkvg);

    build_logk<<<dim3(NTOK / 64, NTOK / 64, NH), 256>>>(wrel, x_res, wdist);

    dim3 gsink(NSTRIPE, NH);
    for (int it = 0; it < NITER; it++) {
        sink_mma<<<gsink, 256>>>(mu, it);
        sink_colfin<<<(NH * NTOK + 255) / 256, 256>>>(nu);
    }

    build_W<<<dim3(NTOK / 256, NH), 256>>>(x_res);
    papply_mma<<<dim3(NTOK / 128, NH), 256>>>(x_res);

    Ptr4 bWo; bWo.p[0] = Wo; bWo.p[1] = Wo; bWo.p[2] = Wo; bWo.p[3] = Wo;
    tc_gemm<<<dim3(DMOD/64, NTOK/128, 2), 256>>>(p_o, bWo, p_part, DMOD, DMOD, DMOD, DMOD/2);
    reduce_add<<<(NTOK*DMOD)/256, 256>>>(h_in, p_part, 2, p_h2, NTOK*DMOD);

    xout_kernel<<<(NTOK + 255) / 256, 256>>>(x_res, gamma, out + OUT_X);

    ln_kernel<<<NTOK, 256>>>(p_h2, ln_fg, ln_fb, p_hf);
    Ptr4 b12; b12.p[0] = W1; b12.p[1] = W2; b12.p[2] = W1; b12.p[3] = W1;
    tc_gemm<<<dim3(2*DFF/64, NTOK/128, 1), 256>>>(p_hf, b12, p_t12, 2*DFF, DMOD, DFF, DMOD);
    silumul_kernel<<<(NTOK * DFF) / 256, 256>>>();
    Ptr4 bW3; bW3.p[0] = W3; bW3.p[1] = W3; bW3.p[2] = W3; bW3.p[3] = W3;
    tc_gemm<<<dim3(DMOD/64, NTOK/128, 4), 256>>>(p_t1, bW3, p_part, DMOD, DFF, DMOD, DFF/4);
    reduce_add<<<(NTOK*DMOD)/256, 256>>>(p_h2, p_part, 4, out, NTOK*DMOD);

    copy_uv_kernel<<<(NH * NTOK + 1023) / 1024, 1024>>>(p_lu, p_lv, out + OUT_LU, out + OUT_LV);
}

// round 13
// speedup vs baseline: 1.2125x; 1.1760x over previous
#include <cuda_runtime.h>
#include <cuda_fp16.h>
#include <cuda_bf16.h>
#include <math.h>

#define NTOK 1280
#define DMOD 512
#define NH   16
#define DH   32
#define DFF  2048
#define NITER 20
#define SBLK 16              // stripe-blocks per head (80 rows each)
#define TPB 5                // 16-row tiles per block
#define WCOLS 40             // W: 32 V + 3 x + 1 ones + 4 pad
#define TW 1288              // smem tile row stride in halves (1280 + 8 pad)
#define TILE_B (16 * TW * 2) // bytes per tile buffer (41216)
#define SMEM_SZ (2 * TILE_B + 2560 + 512 + 64 + 32 + 16)

// ---------------- scratch ----------------
__device__ __nv_bfloat16 g_EK[NH*NTOK*NTOK];  // exp(logK), bf16
__device__ __nv_bfloat16 g_Wt[NH*WCOLS*NTOK]; // W^T per head: [d][m]
__device__ float g_cpart[NH*SBLK*NTOK];       // sinkhorn col partials (16/head)
__device__ float g_hn  [NTOK*DMOD];
__device__ float g_qkvg[NTOK*4*DMOD];         // [q | k | v | gate]
__device__ float g_lu [NH*NTOK];
__device__ float g_lv [NH*NTOK];
__device__ float g_eu [NH*NTOK];
__device__ float g_ev [NH*NTOK];
__device__ float g_xc [NH*NTOK*3];
__device__ float g_rows[NH*NTOK];
__device__ float g_o  [NTOK*DMOD];
__device__ float g_h2 [NTOK*DMOD];
__device__ float g_hf [NTOK*DMOD];
__device__ float g_t12[NTOK*2*DFF];
__device__ float g_t1 [NTOK*DFF];
__device__ float g_part[4*NTOK*DMOD];         // split-K GEMM partials

__constant__ float c_eps[NH] = {0.5f,0.5f,0.5f,0.5f, 1.f,1.f,1.f,1.f,
                                2.f,2.f,2.f,2.f, 4.f,4.f,4.f,4.f};

struct Ptr4 { const float* p[4]; };

// ---------------- utility kernels ----------------
__global__ void copy_uv_kernel(const float* __restrict__ lu, const float* __restrict__ lv,
                               float* __restrict__ o1, float* __restrict__ o2) {
    int i = blockIdx.x * blockDim.x + threadIdx.x;
    if (i < NH*NTOK) { o1[i] = lu[i]; o2[i] = lv[i]; }
}

__global__ void ln_kernel(const float* __restrict__ in, const float* __restrict__ g,
                          const float* __restrict__ b, float* __restrict__ out) {
    int row = blockIdx.x;
    int t = threadIdx.x;
    const float* x = in + (size_t)row * DMOD;
    float v0 = x[t], v1 = x[t + 256];
    __shared__ float red[256];
    red[t] = v0 + v1;
    __syncthreads();
    for (int o = 128; o > 0; o >>= 1) { if (t < o) red[t] += red[t + o]; __syncthreads(); }
    float mean = red[0] * (1.f / DMOD);
    __syncthreads();
    float d0 = v0 - mean, d1 = v1 - mean;
    red[t] = d0 * d0 + d1 * d1;
    __syncthreads();
    for (int o = 128; o > 0; o >>= 1) { if (t < o) red[t] += red[t + o]; __syncthreads(); }
    float r = rsqrtf(red[0] * (1.f / DMOD) + 1e-5f);
    out[(size_t)row * DMOD + t]       = d0 * r * g[t]       + b[t];
    out[(size_t)row * DMOD + t + 256] = d1 * r * g[t + 256] + b[t + 256];
}

__global__ void qkln_kernel(float* __restrict__ base) {
    int gidx = blockIdx.x * 8 + (threadIdx.x >> 5);
    int lane = threadIdx.x & 31;
    if (gidx >= NTOK * NH) return;
    int n = gidx / NH, h = gidx % NH;
    float* p = base + (size_t)n * (4*DMOD) + blockIdx.y * DMOD + h * DH;
    float v = p[lane];
    float s = v;
    for (int o = 16; o; o >>= 1) s += __shfl_xor_sync(0xffffffffu, s, o);
    float mean = s * (1.f / 32.f);
    float d = v - mean;
    float s2 = d * d;
    for (int o = 16; o; o >>= 1) s2 += __shfl_xor_sync(0xffffffffu, s2, o);
    p[lane] = d * rsqrtf(s2 * (1.f / 32.f) + 1e-5f);
}

// ---------------- tensor-core helpers ----------------
__device__ __forceinline__ unsigned f2tf32(float f) {
    unsigned u;
    asm("cvt.rna.tf32.f32 %0, %1;" : "=r"(u) : "f"(f));
    return u;
}

__device__ __forceinline__ void mma_tf32(float c[4], const unsigned a[4], const unsigned b[2]) {
    asm volatile("mma.sync.aligned.m16n8k8.row.col.f32.tf32.tf32.f32 "
        "{%0,%1,%2,%3}, {%4,%5,%6,%7}, {%8,%9}, {%0,%1,%2,%3};"
        : "+f"(c[0]), "+f"(c[1]), "+f"(c[2]), "+f"(c[3])
        : "r"(a[0]), "r"(a[1]), "r"(a[2]), "r"(a[3]), "r"(b[0]), "r"(b[1]));
}

__device__ __forceinline__ void mma_bf16(float c[4], const unsigned a[4], const unsigned b[2]) {
    asm volatile("mma.sync.aligned.m16n8k16.row.col.f32.bf16.bf16.f32 "
        "{%0,%1,%2,%3}, {%4,%5,%6,%7}, {%8,%9}, {%0,%1,%2,%3};"
        : "+f"(c[0]), "+f"(c[1]), "+f"(c[2]), "+f"(c[3])
        : "r"(a[0]), "r"(a[1]), "r"(a[2]), "r"(a[3]), "r"(b[0]), "r"(b[1]));
}

__global__ void tc_gemm(const float* __restrict__ A, Ptr4 B4, float* __restrict__ C,
                        int Nn, int K, int colsPer, int KC) {
    __shared__ float As[32][136];
    __shared__ float Bs[32][72];
    int tid = threadIdx.x;
    int m0 = blockIdx.y * 128, n0 = blockIdx.x * 64;
    const float* B = B4.p[n0 / colsPer] + (size_t)(n0 % colsPer) * K;
    int kbeg = blockIdx.z * KC, kend = kbeg + KC;

    int arow = tid >> 1, akseg = (tid & 1) << 4;
    int brow = tid & 63, bkseg = (tid >> 6) << 3;
    const float* Ap = A + (size_t)(m0 + arow) * K + akseg;
    const float* Bp = B + (size_t)brow * K + bkseg;

    int lane = tid & 31, g = lane >> 2, t = lane & 3;
    int wm = tid >> 6;
    int wn = (tid >> 5) & 1;
    int mBase = wm * 32, nBase = wn * 32;

    float c[2][4][4];
#pragma unroll
    for (int mi = 0; mi < 2; mi++)
#pragma unroll
        for (int ni = 0; ni < 4; ni++)
#pragma unroll
            for (int r = 0; r < 4; r++) c[mi][ni][r] = 0.f;

    for (int k0 = kbeg; k0 < kend; k0 += 32) {
        __syncthreads();
#pragma unroll
        for (int i = 0; i < 4; i++) {
            float4 a4 = *(const float4*)(Ap + k0 + 4 * i);
            As[akseg + 4*i + 0][arow] = __uint_as_float(f2tf32(a4.x));
            As[akseg + 4*i + 1][arow] = __uint_as_float(f2tf32(a4.y));
            As[akseg + 4*i + 2][arow] = __uint_as_float(f2tf32(a4.z));
            As[akseg + 4*i + 3][arow] = __uint_as_float(f2tf32(a4.w));
        }
#pragma unroll
        for (int i = 0; i < 2; i++) {
            float4 b4 = *(const float4*)(Bp + k0 + 4 * i);
            Bs[bkseg + 4*i + 0][brow] = __uint_as_float(f2tf32(b4.x));
            Bs[bkseg + 4*i + 1][brow] = __uint_as_float(f2tf32(b4.y));
            Bs[bkseg + 4*i + 2][brow] = __uint_as_float(f2tf32(b4.z));
            Bs[bkseg + 4*i + 3][brow] = __uint_as_float(f2tf32(b4.w));
        }
        __syncthreads();
#pragma unroll
        for (int ks = 0; ks < 32; ks += 8) {
            unsigned a[2][4], b[4][2];
#pragma unroll
            for (int mi = 0; mi < 2; mi++) {
                int mo = mBase + mi * 16 + g;
                a[mi][0] = __float_as_uint(As[ks + t][mo]);
                a[mi][1] = __float_as_uint(As[ks + t][mo + 8]);
                a[mi][2] = __float_as_uint(As[ks + t + 4][mo]);
                a[mi][3] = __float_as_uint(As[ks + t + 4][mo + 8]);
            }
#pragma unroll
            for (int ni = 0; ni < 4; ni++) {
                int no = nBase + ni * 8 + g;
                b[ni][0] = __float_as_uint(Bs[ks + t][no]);
                b[ni][1] = __float_as_uint(Bs[ks + t + 4][no]);
            }
#pragma unroll
            for (int mi = 0; mi < 2; mi++)
#pragma unroll
                for (int ni = 0; ni < 4; ni++)
                    mma_tf32(c[mi][ni], a[mi], b[ni]);
        }
    }

    float* Co = C + (size_t)blockIdx.z * NTOK * Nn;
#pragma unroll
    for (int mi = 0; mi < 2; mi++) {
        int r0 = m0 + mBase + mi * 16 + g;
#pragma unroll
        for (int ni = 0; ni < 4; ni++) {
            int col = n0 + nBase + ni * 8 + 2 * t;
            *(float2*)(Co + (size_t)r0 * Nn + col)       = make_float2(c[mi][ni][0], c[mi][ni][1]);
            *(float2*)(Co + (size_t)(r0 + 8) * Nn + col) = make_float2(c[mi][ni][2], c[mi][ni][3]);
        }
    }
}

__global__ void reduce_add(const float* __restrict__ R, const float* __restrict__ part,
                           int Z, float* __restrict__ out, int n) {
    int i = blockIdx.x * 256 + threadIdx.x;
    if (i >= n) return;
    float a = R[i];
    for (int z = 0; z < Z; z++) a += part[(size_t)z * n + i];
    out[i] = a;
}

// ---------------- build EK = exp(logK) in bf16 ----------------
__global__ void build_logk(const float* __restrict__ wrel, const float* __restrict__ xres,
                           const float* __restrict__ wdist) {
    __shared__ float Qs[32][68];
    __shared__ float Ks[32][68];
    __shared__ float xa[64][3], xb[64][3];
    int h = blockIdx.z;
    int n0 = blockIdx.y * 64, m0 = blockIdx.x * 64;
    int t = threadIdx.x;

    {
        int r = t >> 2, seg = (t & 3) << 3;
        const float* qp = g_qkvg + (size_t)(n0 + r) * (4*DMOD) + h * DH + seg;
        const float* kp = g_qkvg + (size_t)(m0 + r) * (4*DMOD) + DMOD + h * DH + seg;
#pragma unroll
        for (int i = 0; i < 2; i++) {
            float4 q4 = *(const float4*)(qp + 4*i);
            float4 k4 = *(const float4*)(kp + 4*i);
            Qs[seg + 4*i + 0][r] = q4.x; Qs[seg + 4*i + 1][r] = q4.y;
            Qs[seg + 4*i + 2][r] = q4.z; Qs[seg + 4*i + 3][r] = q4.w;
            Ks[seg + 4*i + 0][r] = k4.x; Ks[seg + 4*i + 1][r] = k4.y;
            Ks[seg + 4*i + 2][r] = k4.z; Ks[seg + 4*i + 3][r] = k4.w;
        }
    }
    if (t < 192) { int r = t / 3, c = t % 3; xa[r][c] = xres[(n0 + r) * 3 + c]; }
    if (t >= 64 && t < 256) {
        int u = t - 64;
        if (u < 192) { int r = u / 3, c = u % 3; xb[r][c] = xres[(m0 + r) * 3 + c]; }
    }
    __syncthreads();

    int tm = t >> 4, tn = t & 15;
    float acc[4][4] = {};
#pragma unroll
    for (int k = 0; k < 32; k++) {
        float4 av = *(const float4*)&Qs[k][tm << 2];
        float4 bv = *(const float4*)&Ks[k][tn << 2];
        float a[4] = {av.x, av.y, av.z, av.w};
        float bb[4] = {bv.x, bv.y, bv.z, bv.w};
#pragma unroll
        for (int i = 0; i < 4; i++)
#pragma unroll
            for (int j = 0; j < 4; j++) acc[i][j] += a[i] * bb[j];
    }

    float inve = 1.f / c_eps[h];
    float wd = wdist[h] * 0.01f;
    const float scale = 0.17677669529663687f;
#pragma unroll
    for (int i = 0; i < 4; i++) {
        int nl = (tm << 2) + i;
        int n = n0 + nl;
        float ax0 = xa[nl][0], ax1 = xa[nl][1], ax2 = xa[nl][2];
        size_t base = ((size_t)h * NTOK + n) * NTOK + m0 + (tn << 2);
        float4 w4 = *(const float4*)(wrel + base);
        float e[4];
#pragma unroll
        for (int j = 0; j < 4; j++) {
            int ml = (tn << 2) + j;
            float dx = ax0 - xb[ml][0];
            float dy = ax1 - xb[ml][1];
            float dz = ax2 - xb[ml][2];
            float d2 = dx * dx + dy * dy + dz * dz;
            float wr = (j == 0) ? w4.x : (j == 1) ? w4.y : (j == 2) ? w4.z : w4.w;
            e[j] = __expf((acc[i][j] * scale + wr - wd * d2) * inve);
        }
        *(__nv_bfloat162*)(g_EK + base)     = __floats2bfloat162_rn(e[0], e[1]);
        *(__nv_bfloat162*)(g_EK + base + 2) = __floats2bfloat162_rn(e[2], e[3]);
    }
}

// ---------------- Sinkhorn: ONE launch per iteration ----------------
// Block owns 80 rows (5 tiles x 16) of one head. Dynamic smem: 2 tile buffers
// (double-buffered cp.async.bulk), prologue recomputes ev from 16 stripe partials.
// Row pass per tile: S = EK@ev; col pass accumulates eu^T@EK into persistent
// MMA accumulators across the 5 tiles; one stripe-partial write per block.
__global__ void sink_mma(const float* __restrict__ mu, const float* __restrict__ nu, int it) {
    extern __shared__ __align__(16) char smem[];
    __nv_bfloat16* tiles = (__nv_bfloat16*)smem;                      // 2 x 16*TW
    unsigned* evu   = (unsigned*)(smem + 2 * TILE_B);                 // 640
    float* rowpart  = (float*)(smem + 2 * TILE_B + 2560);             // 8*16
    float* eusm     = (float*)(smem + 2 * TILE_B + 2560 + 512);       // 16
    unsigned* euu   = (unsigned*)(smem + 2 * TILE_B + 2560 + 512 + 64);  // 8
    unsigned long long* mbar = (unsigned long long*)(smem + 2 * TILE_B + 2560 + 512 + 64 + 32);

    int h = blockIdx.y, sb = blockIdx.x;
    int tid = threadIdx.x, warp = tid >> 5, lane = tid & 31;
    int g = lane >> 2, t = lane & 3;
    int row_base = sb * (TPB * 16);
    float fi = 1.f / (1.f + c_eps[h]);

    unsigned mb0 = (unsigned)__cvta_generic_to_shared(&mbar[0]);
    unsigned mb1 = (unsigned)__cvta_generic_to_shared(&mbar[1]);
    if (tid == 0) {
        asm volatile("mbarrier.init.shared.b64 [%0], 1;" :: "r"(mb0) : "memory");
        asm volatile("mbarrier.init.shared.b64 [%0], 1;" :: "r"(mb1) : "memory");
    }
    __syncthreads();

    // issue tiles 0 and 1
    if (tid == 0) {
#pragma unroll
        for (int b = 0; b < 2; b++) {
            unsigned mb = b ? mb1 : mb0;
            asm volatile("mbarrier.arrive.expect_tx.shared.b64 _, [%0], %1;"
                         :: "r"(mb), "r"(16u * NTOK * 2u) : "memory");
            const __nv_bfloat16* gsrc = g_EK + ((size_t)h * NTOK + row_base + b * 16) * NTOK;
            __nv_bfloat16* tdst = tiles + b * (16 * TW);
#pragma unroll
            for (int r = 0; r < 16; r++) {
                unsigned saddr = (unsigned)__cvta_generic_to_shared(tdst + r * TW);
                asm volatile("cp.async.bulk.shared::cluster.global.mbarrier::complete_tx::bytes "
                             "[%0], [%1], %2, [%3];"
                             :: "r"(saddr), "l"((const void*)(gsrc + (size_t)r * NTOK)),
                                "r"(NTOK * 2u), "r"(mb) : "memory");
            }
        }
    }

    // prologue: reconstruct ev (bf16-packed) from previous iteration's partials
    if (it == 0) {
        for (int i = tid; i < 640; i += 256) evu[i] = 0x3F803F80u;
    } else {
        const float* p = g_cpart + (size_t)h * SBLK * NTOK;
        for (int i = tid; i < 640; i += 256) {
            float T0 = 0.f, T1 = 0.f;
#pragma unroll
            for (int s = 0; s < SBLK; s++) {
                T0 += p[(size_t)s * NTOK + 2 * i];
                T1 += p[(size_t)s * NTOK + 2 * i + 1];
            }
            float e0 = __expf(fi * (__logf(fmaxf(nu[h * NTOK + 2 * i], 1e-8f)) - __logf(T0)));
            float e1 = __expf(fi * (__logf(fmaxf(nu[h * NTOK + 2 * i + 1], 1e-8f)) - __logf(T1)));
            __nv_bfloat162 pk = __floats2bfloat162_rn(e0, e1);
            evu[i] = *(unsigned*)&pk;
        }
    }
    __syncthreads();

    float dacc[20][4];
#pragma unroll
    for (int jj = 0; jj < 20; jj++)
#pragma unroll
        for (int r = 0; r < 4; r++) dacc[jj][r] = 0.f;

    for (int j = 0; j < TPB; j++) {
        int b = j & 1;
        unsigned mb = b ? mb1 : mb0;
        unsigned ph = (j >> 1) & 1;
        {
            unsigned done;
            do {
                asm volatile("{\n\t.reg .pred p;\n\t"
                             "mbarrier.try_wait.parity.shared.b64 p, [%1], %2;\n\t"
                             "selp.u32 %0, 1, 0, p;\n\t}"
                             : "=r"(done) : "r"(mb), "r"(ph) : "memory");
            } while (!done);
        }
        __syncthreads();
        unsigned base = (unsigned)__cvta_generic_to_shared(tiles + b * (16 * TW));

        // row pass: warp w covers k in [w*160,(w+1)*160)
        {
            float c[4] = {0.f, 0.f, 0.f, 0.f};
            int rr = (lane & 7) + ((lane >> 3) & 1) * 8;
            int kh = (lane >> 4) * 8;
#pragma unroll
            for (int jj = 0; jj < 10; jj++) {
                int kc = (warp * 10 + jj) * 16;
                unsigned addr = base + (unsigned)((rr * TW + kc + kh) * 2);
                unsigned a[4];
                asm volatile("ldmatrix.sync.aligned.m8n8.x4.shared.b16 {%0,%1,%2,%3}, [%4];"
                    : "=r"(a[0]), "=r"(a[1]), "=r"(a[2]), "=r"(a[3]) : "r"(addr));
                unsigned bb[2];
                bb[0] = evu[kc / 2 + t];
                bb[1] = evu[kc / 2 + 4 + t];
                mma_bf16(c, a, bb);
            }
            if (t == 0) {
                rowpart[warp * 16 + g] = c[0];
                rowpart[warp * 16 + g + 8] = c[2];
            }
        }
        __syncthreads();
        if (tid < 16) {
            float S = rowpart[tid];
#pragma unroll
            for (int w = 1; w < 8; w++) S += rowpart[w * 16 + tid];
            int n = row_base + j * 16 + tid;
            float lu = fi * (__logf(fmaxf(mu[h * NTOK + n], 1e-8f)) - __logf(S));
            float eu = __expf(lu);
            g_lu[h * NTOK + n] = lu;
            g_eu[h * NTOK + n] = eu;
            eusm[tid] = eu;
        }
        __syncthreads();
        if (tid < 8) {
            __nv_bfloat162 pk = __floats2bfloat162_rn(eusm[2 * tid], eusm[2 * tid + 1]);
            euu[tid] = *(unsigned*)&pk;
        }
        __syncthreads();

        // col pass: accumulate into persistent dacc
        {
            unsigned a[4];
            a[0] = (g == 0) ? euu[t] : 0u;
            a[1] = 0u;
            a[2] = (g == 0) ? euu[4 + t] : 0u;
            a[3] = 0u;
            int rl = lane & 15;
#pragma unroll
            for (int jj = 0; jj < 20; jj++) {
                int n0 = (warp * 20 + jj) * 8;
                unsigned addr = base + (unsigned)((rl * TW + n0) * 2);
                unsigned bb[2];
                asm volatile("ldmatrix.sync.aligned.m8n8.x2.trans.shared.b16 {%0,%1}, [%2];"
                    : "=r"(bb[0]), "=r"(bb[1]) : "r"(addr));
                mma_bf16(dacc[jj], a, bb);
            }
        }
        __syncthreads();   // all reads of tile[b] done before re-fill

        // prefetch tile j+2 into buffer b
        if (tid == 0 && j + 2 < TPB) {
            asm volatile("mbarrier.arrive.expect_tx.shared.b64 _, [%0], %1;"
                         :: "r"(mb), "r"(16u * NTOK * 2u) : "memory");
            const __nv_bfloat16* gsrc = g_EK + ((size_t)h * NTOK + row_base + (j + 2) * 16) * NTOK;
            __nv_bfloat16* tdst = tiles + b * (16 * TW);
#pragma unroll
            for (int r = 0; r < 16; r++) {
                unsigned saddr = (unsigned)__cvta_generic_to_shared(tdst + r * TW);
                asm volatile("cp.async.bulk.shared::cluster.global.mbarrier::complete_tx::bytes "
                             "[%0], [%1], %2, [%3];"
                             :: "r"(saddr), "l"((const void*)(gsrc + (size_t)r * NTOK)),
                                "r"(NTOK * 2u), "r"(mb) : "memory");
            }
        }
    }

    // write stripe partial (lanes 0-3 of each warp hold row-0 results)
    if (g == 0) {
        float* outp = g_cpart + ((size_t)h * SBLK + sb) * NTOK;
#pragma unroll
        for (int jj = 0; jj < 20; jj++) {
            int n0 = (warp * 20 + jj) * 8;
            outp[n0 + 2 * t]     = dacc[jj][0];
            outp[n0 + 2 * t + 1] = dacc[jj][1];
        }
    }
}

// final column finish (outputs lv and ev)
__global__ void sink_colfin(const float* __restrict__ nu) {
    int i = blockIdx.x * 256 + threadIdx.x;
    if (i >= NH * NTOK) return;
    int h = i / NTOK;
    int m = i % NTOK;
    const float* p = g_cpart + (size_t)h * SBLK * NTOK + m;
    float T = 0.f;
#pragma unroll
    for (int s = 0; s < SBLK; s++) T += p[(size_t)s * NTOK];
    float fi = 1.f / (1.f + c_eps[h]);
    float lv = fi * (logf(fmaxf(nu[i], 1e-8f)) - logf(T));
    g_lv[i] = lv;
    g_ev[i] = __expf(lv);
}

// ---------------- build W^T = (diag(ev)[V | x | 1])^T in bf16 ----------------
__global__ void build_W(const float* __restrict__ xres) {
    __shared__ float Vs[256][33];
    __shared__ float evs[256];
    __shared__ float xs[256][3];
    int h = blockIdx.y;
    int m0 = blockIdx.x * 256;
    int tid = threadIdx.x;
    for (int i = tid; i < 256 * 32; i += 256) {
        int r = i >> 5, c = i & 31;
        Vs[r][c] = g_qkvg[(size_t)(m0 + r) * (4*DMOD) + 2*DMOD + h * DH + c];
    }
    evs[tid] = g_ev[h * NTOK + m0 + tid];
    xs[tid][0] = xres[(m0 + tid) * 3 + 0];
    xs[tid][1] = xres[(m0 + tid) * 3 + 1];
    xs[tid][2] = xres[(m0 + tid) * 3 + 2];
    __syncthreads();
    float e = evs[tid];
#pragma unroll
    for (int d = 0; d < WCOLS; d++) {
        float v;
        if (d < 32) v = e * Vs[tid][d];
        else if (d < 35) v = e * xs[tid][d - 32];
        else if (d == 35) v = e;
        else v = 0.f;
        g_Wt[((size_t)h * WCOLS + d) * NTOK + m0 + tid] = __float2bfloat16(v);
    }
}

// ---------------- papply via bf16 MMA: C = EK @ W, then scale by eu ----------------
__global__ void papply_mma(const float* __restrict__ xres) {
    __shared__ unsigned As_u[128 * 20];
    __shared__ unsigned Bs_u[WCOLS * 20];
    __shared__ float Cs[128 * 41];
    __shared__ float eus[128];
    int h = blockIdx.y;
    int n0 = blockIdx.x * 128;
    int tid = threadIdx.x;
    int warp = tid >> 5, lane = tid & 31;
    int g = lane >> 2, t = lane & 3;

    if (tid < 128) eus[tid] = g_eu[h * NTOK + n0 + tid];

    float c[5][4];
#pragma unroll
    for (int nt = 0; nt < 5; nt++)
#pragma unroll
        for (int r = 0; r < 4; r++) c[nt][r] = 0.f;

    int arow = tid >> 1, aq = (tid & 1) * 2;
    for (int k0 = 0; k0 < NTOK; k0 += 32) {
        __syncthreads();
        {
            const uint4* src = (const uint4*)(g_EK + ((size_t)h * NTOK + n0 + arow) * NTOK + k0);
#pragma unroll
            for (int j = 0; j < 2; j++) {
                *(uint4*)(As_u + arow * 20 + (aq + j) * 4) = src[aq + j];
            }
        }
        if (tid < 160) {
            int d = tid >> 2, q = tid & 3;
            const uint4* src = (const uint4*)(g_Wt + ((size_t)h * WCOLS + d) * NTOK + k0);
            *(uint4*)(Bs_u + d * 20 + q * 4) = src[q];
        }
        __syncthreads();
#pragma unroll
        for (int ks2 = 0; ks2 < 16; ks2 += 8) {
            const unsigned* au = As_u + (warp * 16 + g) * 20;
            const unsigned* au8 = au + 8 * 20;
            unsigned a[4];
            a[0] = au[ks2 + t];
            a[1] = au8[ks2 + t];
            a[2] = au[ks2 + t + 4];
            a[3] = au8[ks2 + t + 4];
#pragma unroll
            for (int nt = 0; nt < 5; nt++) {
                const unsigned* bu = Bs_u + (nt * 8 + g) * 20;
                unsigned b[2];
                b[0] = bu[ks2 + t];
                b[1] = bu[ks2 + t + 4];
                mma_bf16(c[nt], a, b);
            }
        }
    }

#pragma unroll
    for (int nt = 0; nt < 5; nt++) {
        int row = warp * 16 + g;
        int col = nt * 8 + 2 * t;
        Cs[row * 41 + col]     = c[nt][0];
        Cs[row * 41 + col + 1] = c[nt][1];
        Cs[(row + 8) * 41 + col]     = c[nt][2];
        Cs[(row + 8) * 41 + col + 1] = c[nt][3];
    }
    __syncthreads();

    for (int i = tid; i < 128 * 32; i += 256) {
        int r = i >> 5, d = i & 31;
        int n = n0 + r;
        float attn = eus[r] * Cs[r * 41 + d];
        float gt = g_qkvg[(size_t)n * (4*DMOD) + 3*DMOD + h * DH + d];
        g_o[(size_t)n * DMOD + h * DH + d] = attn / (1.f + __expf(-gt));
    }
    for (int r = tid; r < 128; r += 256) {
        int n = n0 + r;
        float e = eus[r];
        g_xc[((size_t)h * NTOK + n) * 3 + 0] = e * Cs[r * 41 + 32];
        g_xc[((size_t)h * NTOK + n) * 3 + 1] = e * Cs[r * 41 + 33];
        g_xc[((size_t)h * NTOK + n) * 3 + 2] = e * Cs[r * 41 + 34];
        g_rows[h * NTOK + n] = e * Cs[r * 41 + 35];
    }
}

__global__ void xout_kernel(const float* __restrict__ xres, const float* __restrict__ gamma,
                            float* __restrict__ out) {
    int n = blockIdx.x * 256 + threadIdx.x;
    if (n >= NTOK) return;
    float x0 = xres[n * 3 + 0], x1 = xres[n * 3 + 1], x2 = xres[n * 3 + 2];
    float a0 = 0.f, a1 = 0.f, a2 = 0.f;
    for (int h = 0; h < NH; h++) {
        float r = 1.f / (g_rows[h * NTOK + n] + 1e-8f);
        float gm = gamma[h];
        a0 += gm * (x0 - g_xc[((size_t)h * NTOK + n) * 3 + 0] * r);
        a1 += gm * (x1 - g_xc[((size_t)h * NTOK + n) * 3 + 1] * r);
        a2 += gm * (x2 - g_xc[((size_t)h * NTOK + n) * 3 + 2] * r);
    }
    out[n * 3 + 0] = x0 + a0;
    out[n * 3 + 1] = x1 + a1;
    out[n * 3 + 2] = x2 + a2;
}

__global__ void silumul_kernel() {
    int i = blockIdx.x * 256 + threadIdx.x;
    if (i < NTOK * DFF) {
        int n = i >> 11, j = i & (DFF - 1);
        float a = g_t12[(size_t)n * (2*DFF) + j];
        float b = g_t12[(size_t)n * (2*DFF) + DFF + j];
        g_t1[i] = a / (1.f + __expf(-a)) * b;
    }
}

// ---------------- launch ----------------
extern "C" void kernel_launch(void* const* d_in, const int* in_sizes, int n_in,
                              void* d_out, int out_size) {
    const float* h_in  = (const float*)d_in[0];
    const float* x_res = (const float*)d_in[1];
    const float* mu    = (const float*)d_in[2];
    const float* nu    = (const float*)d_in[3];
    const float* wrel  = (const float*)d_in[4];
    const float* wdist = (const float*)d_in[5];
    const float* ln_ag = (const float*)d_in[7];
    const float* ln_ab = (const float*)d_in[8];
    const float* Wq    = (const float*)d_in[9];
    const float* Wk    = (const float*)d_in[10];
    const float* Wv    = (const float*)d_in[11];
    const float* Wg    = (const float*)d_in[12];
    const float* Wo    = (const float*)d_in[13];
    const float* gamma = (const float*)d_in[14];
    const float* ln_fg = (const float*)d_in[15];
    const float* ln_fb = (const float*)d_in[16];
    const float* W1    = (const float*)d_in[17];
    const float* W2    = (const float*)d_in[18];
    const float* W3    = (const float*)d_in[19];
    float* out = (float*)d_out;

    float *p_hn, *p_qkvg, *p_lu, *p_lv, *p_o, *p_h2, *p_hf, *p_t1, *p_part, *p_t12;
    cudaGetSymbolAddress((void**)&p_hn,     g_hn);
    cudaGetSymbolAddress((void**)&p_qkvg,   g_qkvg);
    cudaGetSymbolAddress((void**)&p_lu,     g_lu);
    cudaGetSymbolAddress((void**)&p_lv,     g_lv);
    cudaGetSymbolAddress((void**)&p_o,      g_o);
    cudaGetSymbolAddress((void**)&p_h2,     g_h2);
    cudaGetSymbolAddress((void**)&p_hf,     g_hf);
    cudaGetSymbolAddress((void**)&p_t1,     g_t1);
    cudaGetSymbolAddress((void**)&p_part,   g_part);
    cudaGetSymbolAddress((void**)&p_t12,    g_t12);

    static bool attr_set = false;
    if (!attr_set) {
        cudaFuncSetAttribute(sink_mma, cudaFuncAttributeMaxDynamicSharedMemorySize, SMEM_SZ);
        attr_set = true;
    }

    const int OUT_X  = NTOK * DMOD;
    const int OUT_LU = OUT_X + NTOK * 3;
    const int OUT_LV = OUT_LU + NH * NTOK;

    ln_kernel<<<NTOK, 256>>>(h_in, ln_ag, ln_ab, p_hn);

    Ptr4 bqkvg; bqkvg.p[0] = Wq; bqkvg.p[1] = Wk; bqkvg.p[2] = Wv; bqkvg.p[3] = Wg;
    tc_gemm<<<dim3(4*DMOD/64, NTOK/128, 1), 256>>>(p_hn, bqkvg, p_qkvg, 4*DMOD, DMOD, DMOD, DMOD);

    qkln_kernel<<<dim3((NTOK * NH) / 8, 2), 256>>>(p_qkvg);

    build_logk<<<dim3(NTOK / 64, NTOK / 64, NH), 256>>>(wrel, x_res, wdist);

    dim3 gsink(SBLK, NH);
    for (int it = 0; it < NITER; it++)
        sink_mma<<<gsink, 256, SMEM_SZ>>>(mu, nu, it);
    sink_colfin<<<(NH * NTOK + 255) / 256, 256>>>(nu);

    build_W<<<dim3(NTOK / 256, NH), 256>>>(x_res);
    papply_mma<<<dim3(NTOK / 128, NH), 256>>>(x_res);

    Ptr4 bWo; bWo.p[0] = Wo; bWo.p[1] = Wo; bWo.p[2] = Wo; bWo.p[3] = Wo;
    tc_gemm<<<dim3(DMOD/64, NTOK/128, 2), 256>>>(p_o, bWo, p_part, DMOD, DMOD, DMOD, DMOD/2);
    reduce_add<<<(NTOK*DMOD)/256, 256>>>(h_in, p_part, 2, p_h2, NTOK*DMOD);

    xout_kernel<<<(NTOK + 255) / 256, 256>>>(x_res, gamma, out + OUT_X);

    ln_kernel<<<NTOK, 256>>>(p_h2, ln_fg, ln_fb, p_hf);
    Ptr4 b12; b12.p[0] = W1; b12.p[1] = W2; b12.p[2] = W1; b12.p[3] = W1;
    tc_gemm<<<dim3(2*DFF/64, NTOK/128, 1), 256>>>(p_hf, b12, p_t12, 2*DFF, DMOD, DFF, DMOD);
    silumul_kernel<<<(NTOK * DFF) / 256, 256>>>();
    Ptr4 bW3; bW3.p[0] = W3; bW3.p[1] = W3; bW3.p[2] = W3; bW3.p[3] = W3;
    tc_gemm<<<dim3(DMOD/64, NTOK/128, 4), 256>>>(p_t1, bW3, p_part, DMOD, DFF, DMOD, DFF/4);
    reduce_add<<<(NTOK*DMOD)/256, 256>>>(p_h2, p_part, 4, out, NTOK*DMOD);

    copy_uv_kernel<<<(NH * NTOK + 1023) / 1024, 1024>>>(p_lu, p_lv, out + OUT_LU, out + OUT_LV);
}